// round 16
// baseline (speedup 1.0000x reference)
#include <cuda_runtime.h>
#include <cuda_fp16.h>
#include <cstdint>
#include <cmath>

#define BB 2
#define LL 1024
#define DM 768
#define DI 1536
#define DS 16
#define DTR 48
#define XD 80            // DTR + 2*DS
#define ROWS (BB*LL)     // 2048
#define KSPLIT 6
#define G2SPLIT 3
#define NCHUNK 8
#define CHL (LL / NCHUNK)   // 128 steps per chunk
#define XPN 128             // padded x_proj output width

// ================= helpers =================================================
__device__ __forceinline__ uint32_t smem_to_u32(const void* p) {
    uint32_t a;
    asm("{ .reg .u64 t; cvta.to.shared.u64 t, %1; cvt.u32.u64 %0, t; }" : "=r"(a) : "l"(p));
    return a;
}
__device__ __forceinline__ void cpasync16(uint32_t dst, const void* src) {
    asm volatile("cp.async.cg.shared.global [%0], [%1], 16;" :: "r"(dst), "l"(src));
}
#define CP_COMMIT() asm volatile("cp.async.commit_group;" ::: "memory")
#define CP_WAIT2()  asm volatile("cp.async.wait_group 2;" ::: "memory")

__device__ __forceinline__ void ldsm4(uint32_t* r, uint32_t addr) {
    asm volatile("ldmatrix.sync.aligned.m8n8.x4.shared.b16 {%0,%1,%2,%3}, [%4];"
        : "=r"(r[0]), "=r"(r[1]), "=r"(r[2]), "=r"(r[3]) : "r"(addr));
}
__device__ __forceinline__ void mma_fp16(float* c, const uint32_t* a, uint32_t b0, uint32_t b1) {
    asm volatile("mma.sync.aligned.m16n8k16.row.col.f32.f16.f16.f32 "
        "{%0,%1,%2,%3}, {%4,%5,%6,%7}, {%8,%9}, {%0,%1,%2,%3};"
        : "+f"(c[0]), "+f"(c[1]), "+f"(c[2]), "+f"(c[3])
        : "r"(a[0]), "r"(a[1]), "r"(a[2]), "r"(a[3]), "r"(b0), "r"(b1));
}

// ================= scratch (device globals; no allocation) =================
__device__ float g_xz[(size_t)ROWS * 2 * DI];
__device__ float g_uc[2][(size_t)ROWS * DI];
__device__ float g_xdbl[2][(size_t)ROWS * XD];
__device__ float g_xpart[2][KSPLIT][(size_t)ROWS * XPN];
__device__ float g_delta[2][(size_t)ROWS * DI];
__device__ float g_c2p[G2SPLIT][(size_t)ROWS * DM];
__device__ float g_P[(size_t)2 * BB * NCHUNK * DI * DS];
__device__ float g_S[(size_t)2 * BB * NCHUNK * DI * DS];
// fp16 operands: activations single, weights hi/lo
__device__ __half g_ah[(size_t)ROWS * DM];
__device__ __half g_w1h[(size_t)(2 * DI) * DM];
__device__ __half g_w1l[(size_t)(2 * DI) * DM];
__device__ __half g_uh[2][(size_t)ROWS * DI];
__device__ __half g_xpwh[2][(size_t)XPN * DI];
__device__ __half g_xpwl[2][(size_t)XPN * DI];
__device__ __half g_ych[(size_t)ROWS * DI];
__device__ __half g_w2h[(size_t)DM * DI];
__device__ __half g_w2l[(size_t)DM * DI];

// ================= fused fp32 -> fp16 conversion ===========================
#define N4_X   (ROWS * DM / 4)
#define N4_W1  (2 * DI * DM / 4)
#define N4_W2  (DM * DI / 4)
#define N4_XP  (XPN * DI / 4)
#define N4_TOT (N4_X + N4_W1 + N4_W2 + 2 * N4_XP)
__global__ void cvt_all(const float* __restrict__ x, const float* __restrict__ w1,
                        const float* __restrict__ w2, const float* __restrict__ xpf,
                        const float* __restrict__ xpr)
{
    int i = blockIdx.x * blockDim.x + threadIdx.x;
    if (i >= N4_TOT) return;
    if (i < N4_X) {
        float4 v = ((const float4*)x)[i];
        ((__half2*)g_ah)[2 * i]     = __floats2half2_rn(v.x, v.y);
        ((__half2*)g_ah)[2 * i + 1] = __floats2half2_rn(v.z, v.w);
        return;
    }
    i -= N4_X;
    const float* s; __half *h, *l;
    bool pad = false;
    if (i < N4_W1) {
        s = w1; h = g_w1h; l = g_w1l;
    } else if (i < N4_W1 + N4_W2) {
        i -= N4_W1; s = w2; h = g_w2h; l = g_w2l;
    } else {
        i -= N4_W1 + N4_W2;
        if (i < N4_XP) { s = xpf; h = g_xpwh[0]; l = g_xpwl[0]; }
        else { i -= N4_XP; s = xpr; h = g_xpwh[1]; l = g_xpwl[1]; }
        pad = (i >= 80 * DI / 4);
    }
    float4 v = pad ? make_float4(0.f, 0.f, 0.f, 0.f) : ((const float4*)s)[i];
    __half h0 = __float2half_rn(v.x), h1 = __float2half_rn(v.y);
    __half h2 = __float2half_rn(v.z), h3 = __float2half_rn(v.w);
    __half l0 = __float2half_rn(v.x - __half2float(h0));
    __half l1 = __float2half_rn(v.y - __half2float(h1));
    __half l2 = __float2half_rn(v.z - __half2float(h2));
    __half l3 = __float2half_rn(v.w - __half2float(h3));
    ((__half2*)h)[2 * i]     = __half2(h0, h1);
    ((__half2*)h)[2 * i + 1] = __half2(h2, h3);
    ((__half2*)l)[2 * i]     = __half2(l0, l1);
    ((__half2*)l)[2 * i + 1] = __half2(l2, l3);
}

// ================= fp16 2-product GEMM: C = A*(Bh+Bl)^T ====================
#define KT 32
#define RB 40
#define TILE_A (128 * RB * 2)
#define TILE_BN (64 * RB * 2)
#define STAGE_B (TILE_A + 2 * TILE_BN)
#define NSTAGE 3
#define GEMM_SMEM (NSTAGE * STAGE_B)        // 61440 B

__global__ void __launch_bounds__(256, 2) gemm_f16(
    const __half* __restrict__ A,
    const __half* __restrict__ Bh, const __half* __restrict__ Bl,
    float* __restrict__ C, int M, int N, int K, int Kper,
    int zdiv, size_t sA, size_t sB, size_t sC)
{
    extern __shared__ char smem[];
    uint32_t sb = smem_to_u32(smem);
    int tid = threadIdx.x;
    int lane = tid & 31, wid = tid >> 5;
    int wm = (wid & 3) * 32, wn = (wid >> 2) * 32;
    int m0 = blockIdx.y * 128, n0 = blockIdx.x * 64;
    int dir = blockIdx.z / zdiv;
    int kz  = blockIdx.z % zdiv;
    A  += (size_t)dir * sA;
    Bh += (size_t)dir * sB; Bl += (size_t)dir * sB;
    C  += (size_t)dir * sC + (size_t)kz * M * N;
    int kbase = kz * Kper;
    const int NC = Kper / KT;

    float acc[2][4][4];
#pragma unroll
    for (int a = 0; a < 2; a++)
#pragma unroll
        for (int b = 0; b < 4; b++)
#pragma unroll
            for (int c = 0; c < 4; c++) acc[a][b][c] = 0.f;

    int rB = tid >> 2, cB = tid & 3;
#define LOAD_STAGE(IT, S)                                                               \
    do {                                                                                \
        uint32_t stg_ = sb + (S) * STAGE_B;                                             \
        int kof_ = kbase + (IT) * KT;                                                   \
        _Pragma("unroll")                                                               \
        for (int i_ = 0; i_ < 2; i_++) {                                                \
            int v_ = tid + i_ * 256;                                                    \
            int r_ = v_ >> 2, c_ = v_ & 3;                                              \
            cpasync16(stg_ + r_ * (RB * 2) + c_ * 16,                                   \
                      A + (size_t)(m0 + r_) * K + kof_ + c_ * 8);                       \
        }                                                                               \
        uint32_t db_ = stg_ + TILE_A + rB * (RB * 2) + cB * 16;                         \
        cpasync16(db_,           Bh + (size_t)(n0 + rB) * K + kof_ + cB * 8);           \
        cpasync16(db_ + TILE_BN, Bl + (size_t)(n0 + rB) * K + kof_ + cB * 8);           \
    } while (0)

    LOAD_STAGE(0, 0); CP_COMMIT();
    LOAD_STAGE(1, 1); CP_COMMIT();

    int stage = 2;
    for (int it = 0; it < NC; it++) {
        if (it + 2 < NC) LOAD_STAGE(it + 2, stage);
        CP_COMMIT();
        if (++stage == NSTAGE) stage = 0;
        CP_WAIT2();
        __syncthreads();
        int cs = it % NSTAGE;
        uint32_t stg = sb + cs * STAGE_B;
#pragma unroll
        for (int ks = 0; ks < 2; ks++) {
            uint32_t aH[2][4];
            uint32_t bh0[4], bl0[4], bh1[4], bl1[4];
            int arow = wm + ((lane >> 3) & 1) * 8 + (lane & 7);
            int acol = ks * 16 + (lane >> 4) * 8;
            int brow = wn + (lane >> 4) * 8 + (lane & 7);
            int bcol = ks * 16 + ((lane >> 3) & 1) * 8;
            uint32_t aoff0 = ((uint32_t)(arow) * RB + acol) * 2;
            uint32_t aoff1 = ((uint32_t)(arow + 16) * RB + acol) * 2;
            uint32_t boff0 = ((uint32_t)(brow) * RB + bcol) * 2;
            uint32_t boff1 = ((uint32_t)(brow + 16) * RB + bcol) * 2;
            ldsm4(aH[0], stg + aoff0);
            ldsm4(aH[1], stg + aoff1);
            ldsm4(bh0, stg + TILE_A + boff0);
            ldsm4(bh1, stg + TILE_A + boff1);
            ldsm4(bl0, stg + TILE_A + TILE_BN + boff0);
            ldsm4(bl1, stg + TILE_A + TILE_BN + boff1);
#pragma unroll
            for (int mt = 0; mt < 2; mt++) {
                mma_fp16(acc[mt][0], aH[mt], bh0[0], bh0[1]);
                mma_fp16(acc[mt][0], aH[mt], bl0[0], bl0[1]);
                mma_fp16(acc[mt][1], aH[mt], bh0[2], bh0[3]);
                mma_fp16(acc[mt][1], aH[mt], bl0[2], bl0[3]);
                mma_fp16(acc[mt][2], aH[mt], bh1[0], bh1[1]);
                mma_fp16(acc[mt][2], aH[mt], bl1[0], bl1[1]);
                mma_fp16(acc[mt][3], aH[mt], bh1[2], bh1[3]);
                mma_fp16(acc[mt][3], aH[mt], bl1[2], bl1[3]);
            }
        }
        __syncthreads();
    }

    int g = lane >> 2, tg = lane & 3;
#pragma unroll
    for (int mt = 0; mt < 2; mt++)
#pragma unroll
        for (int nt = 0; nt < 4; nt++) {
            int row = m0 + wm + mt * 16 + g;
            int col = n0 + wn + nt * 8 + tg * 2;
            *(float2*)&C[(size_t)row * N + col] =
                make_float2(acc[mt][nt][0], acc[mt][nt][1]);
            *(float2*)&C[(size_t)(row + 8) * N + col] =
                make_float2(acc[mt][nt][2], acc[mt][nt][3]);
        }
#undef LOAD_STAGE
}

__global__ void reduce_g2(float* __restrict__ out)
{
    int i = blockIdx.x * blockDim.x + threadIdx.x;
    if (i >= ROWS * DM / 4) return;
    float4 a = ((const float4*)g_c2p[0])[i];
    float4 b = ((const float4*)g_c2p[1])[i];
    float4 c = ((const float4*)g_c2p[2])[i];
    ((float4*)out)[i] = make_float4(a.x + b.x + c.x, a.y + b.y + c.y,
                                    a.z + b.z + c.z, a.w + b.w + c.w);
}

// ================= causal depthwise conv + SiLU (emits u fp32 + fp16) ======
__global__ void conv_silu_kernel(const float* __restrict__ cw_f, const float* __restrict__ cb_f,
                                 const float* __restrict__ cw_r, const float* __restrict__ cb_r)
{
    int c = blockIdx.x * 128 + threadIdx.x;
    int l0 = blockIdx.y * 4;
    int b = blockIdx.z & 1;
    int dir = blockIdx.z >> 1;
    const float* cw = dir ? cw_r : cw_f;
    const float* cb = dir ? cb_r : cb_f;
    float4 w = *(const float4*)(cw + c * 4);
    float bias = cb[c];
    const float* base = g_xz + c;
    float xv[7];
#pragma unroll
    for (int k = 0; k < 7; k++) {
        int j = l0 - 3 + k;
        if (j >= 0) {
            int lsrc = dir ? (LL - 1 - j) : j;
            xv[k] = base[(size_t)(b * LL + lsrc) * (2 * DI)];
        } else xv[k] = 0.f;
    }
    size_t ob = (size_t)(b * LL + l0) * DI + c;
    float* po = g_uc[dir] + ob;
    __half* ph = g_uh[dir] + ob;
#pragma unroll
    for (int i = 0; i < 4; i++) {
        float s = bias + w.x * xv[i] + w.y * xv[i + 1] + w.z * xv[i + 2] + w.w * xv[i + 3];
        float sig = 1.f / (1.f + __expf(-s));
        float v = s * sig;
        po[(size_t)i * DI] = v;
        ph[(size_t)i * DI] = __float2half_rn(v);
    }
}

// ================= x_proj partial reduce ==================================
__global__ void xreduce()
{
    int i = blockIdx.x * blockDim.x + threadIdx.x;
    if (i >= 2 * ROWS * XD) return;
    int dir = i / (ROWS * XD);
    int off = i % (ROWS * XD);
    int row = off / XD, col = off - row * XD;
    float s = 0.f;
#pragma unroll
    for (int k = 0; k < KSPLIT; k++) s += g_xpart[dir][k][(size_t)row * XPN + col];
    g_xdbl[dir][off] = s;
}

// ================= dt proj + softplus (vectorized LDS) =====================
#define DT_SMEM (256 * 49 * 4 + 32 * DTR * 4)
__global__ __launch_bounds__(256) void dtproj_kernel(
    const float* __restrict__ Wf, const float* __restrict__ bf,
    const float* __restrict__ Wr, const float* __restrict__ br)
{
    extern __shared__ float dsm[];
    float* wsm = dsm;
    float* xs  = dsm + 256 * 49;
    int tid = threadIdx.x;
    int dir = blockIdx.z;
    int row0 = blockIdx.x * 32;
    int cbase = blockIdx.y * 256;
    const float* Wdt = dir ? Wr : Wf;
    const float* bdt = dir ? br : bf;
    for (int e = tid; e < 256 * DTR; e += 256) {
        int cl = e / DTR, j = e - cl * DTR;
        wsm[cl * 49 + j] = Wdt[(size_t)cbase * DTR + e];
    }
    for (int e = tid; e < 32 * DTR; e += 256) {
        int r = e / DTR, j = e - r * DTR;
        xs[r * DTR + j] = g_xdbl[dir][(size_t)(row0 + r) * XD + j];
    }
    __syncthreads();
    float w[DTR];
#pragma unroll
    for (int j = 0; j < DTR; j++) w[j] = wsm[tid * 49 + j];
    int c = cbase + tid;
    float bias = bdt[c];
    for (int r = 0; r < 32; r++) {
        const float4* xrow = (const float4*)(xs + r * DTR);
        float acc = bias;
#pragma unroll
        for (int j4 = 0; j4 < DTR / 4; j4++) {
            float4 xv = xrow[j4];
            acc = fmaf(xv.x, w[j4 * 4 + 0], acc);
            acc = fmaf(xv.y, w[j4 * 4 + 1], acc);
            acc = fmaf(xv.z, w[j4 * 4 + 2], acc);
            acc = fmaf(xv.w, w[j4 * 4 + 3], acc);
        }
        float d = (acc > 20.f) ? acc : log1pf(__expf(acc));
        g_delta[dir][(size_t)(row0 + r) * DI + c] = d;
    }
}

// ================= chunked selective scan ==================================
__global__ __launch_bounds__(128) void scan_pass1(
    const float* __restrict__ Alog_f, const float* __restrict__ Alog_r)
{
    int tid = threadIdx.x;
    int lane = tid & 31, warp = tid >> 5;
    int dir = blockIdx.z;
    int b = blockIdx.y >> 3, k = blockIdx.y & 7;
    int q = lane & 3;
    int c = blockIdx.x * 32 + warp * 8 + (lane >> 2);
    const float* Alog = dir ? Alog_r : Alog_f;
    float4 av = *(const float4*)(Alog + c * DS + q * 4);
    float a0 = -__expf(av.x), a1 = -__expf(av.y), a2 = -__expf(av.z), a3 = -__expf(av.w);
    size_t t0 = (size_t)(b * LL + k * CHL);
    const float* dlt = g_delta[dir] + t0 * DI + c;
    const float* uu  = g_uc[dir]    + t0 * DI + c;
    const float* xd  = g_xdbl[dir]  + t0 * XD;
    float P0 = 1.f, P1 = 1.f, P2 = 1.f, P3 = 1.f;
    float h0 = 0.f, h1 = 0.f, h2 = 0.f, h3 = 0.f;
#pragma unroll 4
    for (int t = 0; t < CHL; t++) {
        float d  = dlt[(size_t)t * DI];
        float uv = uu[(size_t)t * DI];
        float4 Bq = *(const float4*)(xd + (size_t)t * XD + DTR + q * 4);
        float du = d * uv;
        float dA0 = __expf(d * a0), dA1 = __expf(d * a1);
        float dA2 = __expf(d * a2), dA3 = __expf(d * a3);
        h0 = fmaf(dA0, h0, du * Bq.x);  P0 *= dA0;
        h1 = fmaf(dA1, h1, du * Bq.y);  P1 *= dA1;
        h2 = fmaf(dA2, h2, du * Bq.z);  P2 *= dA2;
        h3 = fmaf(dA3, h3, du * Bq.w);  P3 *= dA3;
    }
    size_t o = ((((size_t)dir * BB + b) * NCHUNK + k) * DI + c) * DS + q * 4;
    *(float4*)(g_P + o) = make_float4(P0, P1, P2, P3);
    *(float4*)(g_S + o) = make_float4(h0, h1, h2, h3);
}

// Pass 2 fused with combine: block handles forward chunk k AND reverse chunk
// NCHUNK-1-k (same output rows, local step t <-> CHL-1-t), gates with z, and
// writes fp16 ych directly. Eliminates the y buffer round-trip entirely.
__global__ __launch_bounds__(128) void scan_pass2_fused(
    const float* __restrict__ Alog_f, const float* __restrict__ D_f,
    const float* __restrict__ Alog_r, const float* __restrict__ D_r)
{
    __shared__ float yrs[CHL * 32];
    int tid = threadIdx.x;
    int lane = tid & 31, warp = tid >> 5;
    int b = blockIdx.y >> 3, k = blockIdx.y & 7;
    int q = lane & 3;
    int ci = warp * 8 + (lane >> 2);
    int c = blockIdx.x * 32 + ci;

    // ---- Phase A: reverse direction, chunk kr = NCHUNK-1-k ----
    {
        int kr = NCHUNK - 1 - k;
        float4 av = *(const float4*)(Alog_r + c * DS + q * 4);
        float a0 = -__expf(av.x), a1 = -__expf(av.y), a2 = -__expf(av.z), a3 = -__expf(av.w);
        float Dv = D_r[c];
        float h0 = 0.f, h1 = 0.f, h2 = 0.f, h3 = 0.f;
        size_t ob = (((size_t)1 * BB + b) * NCHUNK * DI + c) * DS + q * 4;
        for (int kk = 0; kk < kr; kk++) {
            size_t o = ob + (size_t)kk * DI * DS;
            float4 P = *(const float4*)(g_P + o);
            float4 S = *(const float4*)(g_S + o);
            h0 = fmaf(P.x, h0, S.x);
            h1 = fmaf(P.y, h1, S.y);
            h2 = fmaf(P.z, h2, S.z);
            h3 = fmaf(P.w, h3, S.w);
        }
        size_t t0 = (size_t)(b * LL + kr * CHL);
        const float* dlt = g_delta[1] + t0 * DI + c;
        const float* uu  = g_uc[1]    + t0 * DI + c;
        const float* xd  = g_xdbl[1]  + t0 * XD;
#pragma unroll 4
        for (int t = 0; t < CHL; t++) {
            float d  = dlt[(size_t)t * DI];
            float uv = uu[(size_t)t * DI];
            float4 Bq = *(const float4*)(xd + (size_t)t * XD + DTR + q * 4);
            float4 Cq = *(const float4*)(xd + (size_t)t * XD + DTR + DS + q * 4);
            float du = d * uv;
            float dA0 = __expf(d * a0), dA1 = __expf(d * a1);
            float dA2 = __expf(d * a2), dA3 = __expf(d * a3);
            h0 = fmaf(dA0, h0, du * Bq.x);
            h1 = fmaf(dA1, h1, du * Bq.y);
            h2 = fmaf(dA2, h2, du * Bq.z);
            h3 = fmaf(dA3, h3, du * Bq.w);
            float p = h0 * Cq.x;
            p = fmaf(h1, Cq.y, p);
            p = fmaf(h2, Cq.z, p);
            p = fmaf(h3, Cq.w, p);
            p += __shfl_xor_sync(0xffffffffu, p, 1);
            p += __shfl_xor_sync(0xffffffffu, p, 2);
            if (q == 0) yrs[t * 32 + ci] = fmaf(uv, Dv, p);
        }
    }
    __syncthreads();
    // ---- Phase B: forward direction, chunk k; combine + gate + store ------
    {
        float4 av = *(const float4*)(Alog_f + c * DS + q * 4);
        float a0 = -__expf(av.x), a1 = -__expf(av.y), a2 = -__expf(av.z), a3 = -__expf(av.w);
        float Dv = D_f[c];
        float h0 = 0.f, h1 = 0.f, h2 = 0.f, h3 = 0.f;
        size_t ob = (((size_t)0 * BB + b) * NCHUNK * DI + c) * DS + q * 4;
        for (int kk = 0; kk < k; kk++) {
            size_t o = ob + (size_t)kk * DI * DS;
            float4 P = *(const float4*)(g_P + o);
            float4 S = *(const float4*)(g_S + o);
            h0 = fmaf(P.x, h0, S.x);
            h1 = fmaf(P.y, h1, S.y);
            h2 = fmaf(P.z, h2, S.z);
            h3 = fmaf(P.w, h3, S.w);
        }
        size_t t0 = (size_t)(b * LL + k * CHL);
        const float* dlt = g_delta[0] + t0 * DI + c;
        const float* uu  = g_uc[0]    + t0 * DI + c;
        const float* xd  = g_xdbl[0]  + t0 * XD;
#pragma unroll 4
        for (int t = 0; t < CHL; t++) {
            float d  = dlt[(size_t)t * DI];
            float uv = uu[(size_t)t * DI];
            float4 Bq = *(const float4*)(xd + (size_t)t * XD + DTR + q * 4);
            float4 Cq = *(const float4*)(xd + (size_t)t * XD + DTR + DS + q * 4);
            float du = d * uv;
            float dA0 = __expf(d * a0), dA1 = __expf(d * a1);
            float dA2 = __expf(d * a2), dA3 = __expf(d * a3);
            h0 = fmaf(dA0, h0, du * Bq.x);
            h1 = fmaf(dA1, h1, du * Bq.y);
            h2 = fmaf(dA2, h2, du * Bq.z);
            h3 = fmaf(dA3, h3, du * Bq.w);
            float p = h0 * Cq.x;
            p = fmaf(h1, Cq.y, p);
            p = fmaf(h2, Cq.z, p);
            p = fmaf(h3, Cq.w, p);
            p += __shfl_xor_sync(0xffffffffu, p, 1);
            p += __shfl_xor_sync(0xffffffffu, p, 2);
            if (q == 0) {
                float yf = fmaf(uv, Dv, p);
                float yr = yrs[(CHL - 1 - t) * 32 + ci];
                size_t gi = t0 + t;
                float z = g_xz[gi * (2 * DI) + DI + c];
                float sig = 1.f / (1.f + __expf(-z));
                g_ych[gi * DI + c] = __float2half_rn((yf + yr) * (z * sig));
            }
        }
    }
}

// ================= launch ==================================================
extern "C" void kernel_launch(void* const* d_in, const int* in_sizes, int n_in,
                              void* d_out, int out_size)
{
    const float* x      = (const float*)d_in[0];
    const float* in_w   = (const float*)d_in[1];
    const float* out_w  = (const float*)d_in[2];
    const float* cw_f   = (const float*)d_in[3];
    const float* cb_f   = (const float*)d_in[4];
    const float* xp_f   = (const float*)d_in[5];
    const float* dtw_f  = (const float*)d_in[6];
    const float* dtb_f  = (const float*)d_in[7];
    const float* Alog_f = (const float*)d_in[8];
    const float* D_f    = (const float*)d_in[9];
    const float* cw_r   = (const float*)d_in[10];
    const float* cb_r   = (const float*)d_in[11];
    const float* xp_r   = (const float*)d_in[12];
    const float* dtw_r  = (const float*)d_in[13];
    const float* dtb_r  = (const float*)d_in[14];
    const float* Alog_r = (const float*)d_in[15];
    const float* D_r    = (const float*)d_in[16];
    float* out = (float*)d_out;

    cudaFuncSetAttribute(gemm_f16, cudaFuncAttributeMaxDynamicSharedMemorySize, GEMM_SMEM);
    cudaFuncSetAttribute(dtproj_kernel, cudaFuncAttributeMaxDynamicSharedMemorySize, DT_SMEM);

    float *xz, *c2p, *xpart;
    __half *ah, *w1h, *w1l, *ych, *w2h, *w2l, *uh, *xpwh, *xpwl;
    cudaGetSymbolAddress((void**)&xz,    g_xz);
    cudaGetSymbolAddress((void**)&c2p,   g_c2p);
    cudaGetSymbolAddress((void**)&xpart, g_xpart);
    cudaGetSymbolAddress((void**)&ah,    g_ah);
    cudaGetSymbolAddress((void**)&w1h,   g_w1h);
    cudaGetSymbolAddress((void**)&w1l,   g_w1l);
    cudaGetSymbolAddress((void**)&ych,   g_ych);
    cudaGetSymbolAddress((void**)&w2h,   g_w2h);
    cudaGetSymbolAddress((void**)&w2l,   g_w2l);
    cudaGetSymbolAddress((void**)&uh,    g_uh);
    cudaGetSymbolAddress((void**)&xpwh,  g_xpwh);
    cudaGetSymbolAddress((void**)&xpwl,  g_xpwl);

    const size_t UD = (size_t)ROWS * DI;
    const size_t WD = (size_t)XPN * DI;
    const size_t PD = (size_t)KSPLIT * ROWS * XPN;

    // 1. convert all GEMM inputs
    cvt_all<<<(N4_TOT + 255) / 256, 256>>>(x, in_w, out_w, xp_f, xp_r);
    // 2. xz = x @ in_w^T
    gemm_f16<<<dim3((2 * DI) / 64, ROWS / 128, 1), 256, GEMM_SMEM>>>(
        ah, w1h, w1l, xz, ROWS, 2 * DI, DM, DM, 1, 0, 0, 0);
    // 3. conv + silu
    conv_silu_kernel<<<dim3(DI / 128, LL / 4, BB * 2), 128>>>(cw_f, cb_f, cw_r, cb_r);
    // 4. x_proj: both dirs in one launch, then reduce
    gemm_f16<<<dim3(XPN / 64, ROWS / 128, 2 * KSPLIT), 256, GEMM_SMEM>>>(
        (const __half*)uh, (const __half*)xpwh, (const __half*)xpwl,
        xpart, ROWS, XPN, DI, DI / KSPLIT, KSPLIT, UD, WD, PD);
    xreduce<<<(2 * ROWS * XD + 255) / 256, 256>>>();
    // 5. dt projection + softplus
    dtproj_kernel<<<dim3(ROWS / 32, DI / 256, 2), 256, DT_SMEM>>>(dtw_f, dtb_f, dtw_r, dtb_r);
    // 6. chunked selective scan: pass1, then fused pass2+combine
    scan_pass1<<<dim3(DI / 32, BB * NCHUNK, 2), 128>>>(Alog_f, Alog_r);
    scan_pass2_fused<<<dim3(DI / 32, BB * NCHUNK), 128>>>(Alog_f, D_f, Alog_r, D_r);
    // 7. out = ycomb @ out_w^T (split-K x3 + reduce)
    gemm_f16<<<dim3(DM / 64, ROWS / 128, G2SPLIT), 256, GEMM_SMEM>>>(
        ych, w2h, w2l, c2p, ROWS, DM, DI, DI / G2SPLIT, G2SPLIT, 0, 0, 0);
    reduce_g2<<<(ROWS * DM / 4 + 255) / 256, 256>>>(out);
}

// round 17
// speedup vs baseline: 1.1689x; 1.1689x over previous
#include <cuda_runtime.h>
#include <cuda_fp16.h>
#include <cstdint>
#include <cmath>

#define BB 2
#define LL 1024
#define DM 768
#define DI 1536
#define DS 16
#define DTR 48
#define XD 80            // DTR + 2*DS
#define ROWS (BB*LL)     // 2048
#define KSPLIT 6
#define G2SPLIT 3
#define NCHUNK 8
#define CHL (LL / NCHUNK)   // 128 steps per chunk
#define XPN 128             // padded x_proj output width

// ================= helpers =================================================
__device__ __forceinline__ uint32_t smem_to_u32(const void* p) {
    uint32_t a;
    asm("{ .reg .u64 t; cvta.to.shared.u64 t, %1; cvt.u32.u64 %0, t; }" : "=r"(a) : "l"(p));
    return a;
}
__device__ __forceinline__ void cpasync16(uint32_t dst, const void* src) {
    asm volatile("cp.async.cg.shared.global [%0], [%1], 16;" :: "r"(dst), "l"(src));
}
#define CP_COMMIT() asm volatile("cp.async.commit_group;" ::: "memory")
#define CP_WAIT2()  asm volatile("cp.async.wait_group 2;" ::: "memory")

__device__ __forceinline__ void ldsm4(uint32_t* r, uint32_t addr) {
    asm volatile("ldmatrix.sync.aligned.m8n8.x4.shared.b16 {%0,%1,%2,%3}, [%4];"
        : "=r"(r[0]), "=r"(r[1]), "=r"(r[2]), "=r"(r[3]) : "r"(addr));
}
__device__ __forceinline__ void mma_fp16(float* c, const uint32_t* a, uint32_t b0, uint32_t b1) {
    asm volatile("mma.sync.aligned.m16n8k16.row.col.f32.f16.f16.f32 "
        "{%0,%1,%2,%3}, {%4,%5,%6,%7}, {%8,%9}, {%0,%1,%2,%3};"
        : "+f"(c[0]), "+f"(c[1]), "+f"(c[2]), "+f"(c[3])
        : "r"(a[0]), "r"(a[1]), "r"(a[2]), "r"(a[3]), "r"(b0), "r"(b1));
}

// ================= scratch (device globals; no allocation) =================
__device__ float g_xz[(size_t)ROWS * 2 * DI];
__device__ float g_uc[2][(size_t)ROWS * DI];
__device__ float g_xdbl[2][(size_t)ROWS * XD];
__device__ float g_xpart[2][KSPLIT][(size_t)ROWS * XPN];
__device__ float g_delta[2][(size_t)ROWS * DI];
__device__ __half g_y[2][(size_t)ROWS * DI];     // y stored fp16 (feeds fp16 GEMM2 anyway)
__device__ float g_c2p[G2SPLIT][(size_t)ROWS * DM];
__device__ float g_P[(size_t)2 * BB * NCHUNK * DI * DS];
__device__ float g_S[(size_t)2 * BB * NCHUNK * DI * DS];
// fp16 operands: activations single, weights hi/lo
__device__ __half g_ah[(size_t)ROWS * DM];
__device__ __half g_w1h[(size_t)(2 * DI) * DM];
__device__ __half g_w1l[(size_t)(2 * DI) * DM];
__device__ __half g_uh[2][(size_t)ROWS * DI];
__device__ __half g_xpwh[2][(size_t)XPN * DI];
__device__ __half g_xpwl[2][(size_t)XPN * DI];
__device__ __half g_ych[(size_t)ROWS * DI];
__device__ __half g_w2h[(size_t)DM * DI];
__device__ __half g_w2l[(size_t)DM * DI];

// ================= fused fp32 -> fp16 conversion ===========================
#define N4_X   (ROWS * DM / 4)
#define N4_W1  (2 * DI * DM / 4)
#define N4_W2  (DM * DI / 4)
#define N4_XP  (XPN * DI / 4)
#define N4_TOT (N4_X + N4_W1 + N4_W2 + 2 * N4_XP)
__global__ void cvt_all(const float* __restrict__ x, const float* __restrict__ w1,
                        const float* __restrict__ w2, const float* __restrict__ xpf,
                        const float* __restrict__ xpr)
{
    int i = blockIdx.x * blockDim.x + threadIdx.x;
    if (i >= N4_TOT) return;
    if (i < N4_X) {
        float4 v = ((const float4*)x)[i];
        ((__half2*)g_ah)[2 * i]     = __floats2half2_rn(v.x, v.y);
        ((__half2*)g_ah)[2 * i + 1] = __floats2half2_rn(v.z, v.w);
        return;
    }
    i -= N4_X;
    const float* s; __half *h, *l;
    bool pad = false;
    if (i < N4_W1) {
        s = w1; h = g_w1h; l = g_w1l;
    } else if (i < N4_W1 + N4_W2) {
        i -= N4_W1; s = w2; h = g_w2h; l = g_w2l;
    } else {
        i -= N4_W1 + N4_W2;
        if (i < N4_XP) { s = xpf; h = g_xpwh[0]; l = g_xpwl[0]; }
        else { i -= N4_XP; s = xpr; h = g_xpwh[1]; l = g_xpwl[1]; }
        pad = (i >= 80 * DI / 4);
    }
    float4 v = pad ? make_float4(0.f, 0.f, 0.f, 0.f) : ((const float4*)s)[i];
    __half h0 = __float2half_rn(v.x), h1 = __float2half_rn(v.y);
    __half h2 = __float2half_rn(v.z), h3 = __float2half_rn(v.w);
    __half l0 = __float2half_rn(v.x - __half2float(h0));
    __half l1 = __float2half_rn(v.y - __half2float(h1));
    __half l2 = __float2half_rn(v.z - __half2float(h2));
    __half l3 = __float2half_rn(v.w - __half2float(h3));
    ((__half2*)h)[2 * i]     = __half2(h0, h1);
    ((__half2*)h)[2 * i + 1] = __half2(h2, h3);
    ((__half2*)l)[2 * i]     = __half2(l0, l1);
    ((__half2*)l)[2 * i + 1] = __half2(l2, l3);
}

// ================= fp16 2-product GEMM: C = A*(Bh+Bl)^T ====================
#define KT 32
#define RB 40
#define TILE_A (128 * RB * 2)
#define TILE_BN (64 * RB * 2)
#define STAGE_B (TILE_A + 2 * TILE_BN)
#define NSTAGE 3
#define GEMM_SMEM (NSTAGE * STAGE_B)        // 61440 B

__global__ void __launch_bounds__(256, 2) gemm_f16(
    const __half* __restrict__ A,
    const __half* __restrict__ Bh, const __half* __restrict__ Bl,
    float* __restrict__ C, int M, int N, int K, int Kper,
    int zdiv, size_t sA, size_t sB, size_t sC)
{
    extern __shared__ char smem[];
    uint32_t sb = smem_to_u32(smem);
    int tid = threadIdx.x;
    int lane = tid & 31, wid = tid >> 5;
    int wm = (wid & 3) * 32, wn = (wid >> 2) * 32;
    int m0 = blockIdx.y * 128, n0 = blockIdx.x * 64;
    int dir = blockIdx.z / zdiv;
    int kz  = blockIdx.z % zdiv;
    A  += (size_t)dir * sA;
    Bh += (size_t)dir * sB; Bl += (size_t)dir * sB;
    C  += (size_t)dir * sC + (size_t)kz * M * N;
    int kbase = kz * Kper;
    const int NC = Kper / KT;

    float acc[2][4][4];
#pragma unroll
    for (int a = 0; a < 2; a++)
#pragma unroll
        for (int b = 0; b < 4; b++)
#pragma unroll
            for (int c = 0; c < 4; c++) acc[a][b][c] = 0.f;

    int rB = tid >> 2, cB = tid & 3;
#define LOAD_STAGE(IT, S)                                                               \
    do {                                                                                \
        uint32_t stg_ = sb + (S) * STAGE_B;                                             \
        int kof_ = kbase + (IT) * KT;                                                   \
        _Pragma("unroll")                                                               \
        for (int i_ = 0; i_ < 2; i_++) {                                                \
            int v_ = tid + i_ * 256;                                                    \
            int r_ = v_ >> 2, c_ = v_ & 3;                                              \
            cpasync16(stg_ + r_ * (RB * 2) + c_ * 16,                                   \
                      A + (size_t)(m0 + r_) * K + kof_ + c_ * 8);                       \
        }                                                                               \
        uint32_t db_ = stg_ + TILE_A + rB * (RB * 2) + cB * 16;                         \
        cpasync16(db_,           Bh + (size_t)(n0 + rB) * K + kof_ + cB * 8);           \
        cpasync16(db_ + TILE_BN, Bl + (size_t)(n0 + rB) * K + kof_ + cB * 8);           \
    } while (0)

    LOAD_STAGE(0, 0); CP_COMMIT();
    LOAD_STAGE(1, 1); CP_COMMIT();

    int stage = 2;
    for (int it = 0; it < NC; it++) {
        if (it + 2 < NC) LOAD_STAGE(it + 2, stage);
        CP_COMMIT();
        if (++stage == NSTAGE) stage = 0;
        CP_WAIT2();
        __syncthreads();
        int cs = it % NSTAGE;
        uint32_t stg = sb + cs * STAGE_B;
#pragma unroll
        for (int ks = 0; ks < 2; ks++) {
            uint32_t aH[2][4];
            uint32_t bh0[4], bl0[4], bh1[4], bl1[4];
            int arow = wm + ((lane >> 3) & 1) * 8 + (lane & 7);
            int acol = ks * 16 + (lane >> 4) * 8;
            int brow = wn + (lane >> 4) * 8 + (lane & 7);
            int bcol = ks * 16 + ((lane >> 3) & 1) * 8;
            uint32_t aoff0 = ((uint32_t)(arow) * RB + acol) * 2;
            uint32_t aoff1 = ((uint32_t)(arow + 16) * RB + acol) * 2;
            uint32_t boff0 = ((uint32_t)(brow) * RB + bcol) * 2;
            uint32_t boff1 = ((uint32_t)(brow + 16) * RB + bcol) * 2;
            ldsm4(aH[0], stg + aoff0);
            ldsm4(aH[1], stg + aoff1);
            ldsm4(bh0, stg + TILE_A + boff0);
            ldsm4(bh1, stg + TILE_A + boff1);
            ldsm4(bl0, stg + TILE_A + TILE_BN + boff0);
            ldsm4(bl1, stg + TILE_A + TILE_BN + boff1);
#pragma unroll
            for (int mt = 0; mt < 2; mt++) {
                mma_fp16(acc[mt][0], aH[mt], bh0[0], bh0[1]);
                mma_fp16(acc[mt][0], aH[mt], bl0[0], bl0[1]);
                mma_fp16(acc[mt][1], aH[mt], bh0[2], bh0[3]);
                mma_fp16(acc[mt][1], aH[mt], bl0[2], bl0[3]);
                mma_fp16(acc[mt][2], aH[mt], bh1[0], bh1[1]);
                mma_fp16(acc[mt][2], aH[mt], bl1[0], bl1[1]);
                mma_fp16(acc[mt][3], aH[mt], bh1[2], bh1[3]);
                mma_fp16(acc[mt][3], aH[mt], bl1[2], bl1[3]);
            }
        }
        __syncthreads();
    }

    int g = lane >> 2, tg = lane & 3;
#pragma unroll
    for (int mt = 0; mt < 2; mt++)
#pragma unroll
        for (int nt = 0; nt < 4; nt++) {
            int row = m0 + wm + mt * 16 + g;
            int col = n0 + wn + nt * 8 + tg * 2;
            *(float2*)&C[(size_t)row * N + col] =
                make_float2(acc[mt][nt][0], acc[mt][nt][1]);
            *(float2*)&C[(size_t)(row + 8) * N + col] =
                make_float2(acc[mt][nt][2], acc[mt][nt][3]);
        }
#undef LOAD_STAGE
}

__global__ void reduce_g2(float* __restrict__ out)
{
    int i = blockIdx.x * blockDim.x + threadIdx.x;
    if (i >= ROWS * DM / 4) return;
    float4 a = ((const float4*)g_c2p[0])[i];
    float4 b = ((const float4*)g_c2p[1])[i];
    float4 c = ((const float4*)g_c2p[2])[i];
    ((float4*)out)[i] = make_float4(a.x + b.x + c.x, a.y + b.y + c.y,
                                    a.z + b.z + c.z, a.w + b.w + c.w);
}

// ================= causal depthwise conv + SiLU (emits u fp32 + fp16) ======
__global__ void conv_silu_kernel(const float* __restrict__ cw_f, const float* __restrict__ cb_f,
                                 const float* __restrict__ cw_r, const float* __restrict__ cb_r)
{
    int c = blockIdx.x * 128 + threadIdx.x;
    int l0 = blockIdx.y * 4;
    int b = blockIdx.z & 1;
    int dir = blockIdx.z >> 1;
    const float* cw = dir ? cw_r : cw_f;
    const float* cb = dir ? cb_r : cb_f;
    float4 w = *(const float4*)(cw + c * 4);
    float bias = cb[c];
    const float* base = g_xz + c;
    float xv[7];
#pragma unroll
    for (int k = 0; k < 7; k++) {
        int j = l0 - 3 + k;
        if (j >= 0) {
            int lsrc = dir ? (LL - 1 - j) : j;
            xv[k] = base[(size_t)(b * LL + lsrc) * (2 * DI)];
        } else xv[k] = 0.f;
    }
    size_t ob = (size_t)(b * LL + l0) * DI + c;
    float* po = g_uc[dir] + ob;
    __half* ph = g_uh[dir] + ob;
#pragma unroll
    for (int i = 0; i < 4; i++) {
        float s = bias + w.x * xv[i] + w.y * xv[i + 1] + w.z * xv[i + 2] + w.w * xv[i + 3];
        float sig = 1.f / (1.f + __expf(-s));
        float v = s * sig;
        po[(size_t)i * DI] = v;
        ph[(size_t)i * DI] = __float2half_rn(v);
    }
}

// ================= x_proj partial reduce ==================================
__global__ void xreduce()
{
    int i = blockIdx.x * blockDim.x + threadIdx.x;
    if (i >= 2 * ROWS * XD) return;
    int dir = i / (ROWS * XD);
    int off = i % (ROWS * XD);
    int row = off / XD, col = off - row * XD;
    float s = 0.f;
#pragma unroll
    for (int k = 0; k < KSPLIT; k++) s += g_xpart[dir][k][(size_t)row * XPN + col];
    g_xdbl[dir][off] = s;
}

// ================= dt proj + softplus (vectorized LDS) =====================
#define DT_SMEM (256 * 49 * 4 + 32 * DTR * 4)
__global__ __launch_bounds__(256) void dtproj_kernel(
    const float* __restrict__ Wf, const float* __restrict__ bf,
    const float* __restrict__ Wr, const float* __restrict__ br)
{
    extern __shared__ float dsm[];
    float* wsm = dsm;
    float* xs  = dsm + 256 * 49;
    int tid = threadIdx.x;
    int dir = blockIdx.z;
    int row0 = blockIdx.x * 32;
    int cbase = blockIdx.y * 256;
    const float* Wdt = dir ? Wr : Wf;
    const float* bdt = dir ? br : bf;
    for (int e = tid; e < 256 * DTR; e += 256) {
        int cl = e / DTR, j = e - cl * DTR;
        wsm[cl * 49 + j] = Wdt[(size_t)cbase * DTR + e];
    }
    for (int e = tid; e < 32 * DTR; e += 256) {
        int r = e / DTR, j = e - r * DTR;
        xs[r * DTR + j] = g_xdbl[dir][(size_t)(row0 + r) * XD + j];
    }
    __syncthreads();
    float w[DTR];
#pragma unroll
    for (int j = 0; j < DTR; j++) w[j] = wsm[tid * 49 + j];
    int c = cbase + tid;
    float bias = bdt[c];
    for (int r = 0; r < 32; r++) {
        const float4* xrow = (const float4*)(xs + r * DTR);
        float acc = bias;
#pragma unroll
        for (int j4 = 0; j4 < DTR / 4; j4++) {
            float4 xv = xrow[j4];
            acc = fmaf(xv.x, w[j4 * 4 + 0], acc);
            acc = fmaf(xv.y, w[j4 * 4 + 1], acc);
            acc = fmaf(xv.z, w[j4 * 4 + 2], acc);
            acc = fmaf(xv.w, w[j4 * 4 + 3], acc);
        }
        float d = (acc > 20.f) ? acc : log1pf(__expf(acc));
        g_delta[dir][(size_t)(row0 + r) * DI + c] = d;
    }
}

// ================= chunked selective scan ==================================
__global__ __launch_bounds__(128) void scan_pass1(
    const float* __restrict__ Alog_f, const float* __restrict__ Alog_r)
{
    int tid = threadIdx.x;
    int lane = tid & 31, warp = tid >> 5;
    int dir = blockIdx.z;
    int b = blockIdx.y >> 3, k = blockIdx.y & 7;
    int q = lane & 3;
    int c = blockIdx.x * 32 + warp * 8 + (lane >> 2);
    const float* Alog = dir ? Alog_r : Alog_f;
    float4 av = *(const float4*)(Alog + c * DS + q * 4);
    float a0 = -__expf(av.x), a1 = -__expf(av.y), a2 = -__expf(av.z), a3 = -__expf(av.w);
    size_t t0 = (size_t)(b * LL + k * CHL);
    const float* dlt = g_delta[dir] + t0 * DI + c;
    const float* uu  = g_uc[dir]    + t0 * DI + c;
    const float* xd  = g_xdbl[dir]  + t0 * XD;
    float P0 = 1.f, P1 = 1.f, P2 = 1.f, P3 = 1.f;
    float h0 = 0.f, h1 = 0.f, h2 = 0.f, h3 = 0.f;
#pragma unroll 4
    for (int t = 0; t < CHL; t++) {
        float d  = dlt[(size_t)t * DI];
        float uv = uu[(size_t)t * DI];
        float4 Bq = *(const float4*)(xd + (size_t)t * XD + DTR + q * 4);
        float du = d * uv;
        float dA0 = __expf(d * a0), dA1 = __expf(d * a1);
        float dA2 = __expf(d * a2), dA3 = __expf(d * a3);
        h0 = fmaf(dA0, h0, du * Bq.x);  P0 *= dA0;
        h1 = fmaf(dA1, h1, du * Bq.y);  P1 *= dA1;
        h2 = fmaf(dA2, h2, du * Bq.z);  P2 *= dA2;
        h3 = fmaf(dA3, h3, du * Bq.w);  P3 *= dA3;
    }
    size_t o = ((((size_t)dir * BB + b) * NCHUNK + k) * DI + c) * DS + q * 4;
    *(float4*)(g_P + o) = make_float4(P0, P1, P2, P3);
    *(float4*)(g_S + o) = make_float4(h0, h1, h2, h3);
}

__global__ __launch_bounds__(128) void scan_pass2(
    const float* __restrict__ Alog_f, const float* __restrict__ D_f,
    const float* __restrict__ Alog_r, const float* __restrict__ D_r)
{
    int tid = threadIdx.x;
    int lane = tid & 31, warp = tid >> 5;
    int dir = blockIdx.z;
    int b = blockIdx.y >> 3, k = blockIdx.y & 7;
    int q = lane & 3;
    int c = blockIdx.x * 32 + warp * 8 + (lane >> 2);
    const float* Alog = dir ? Alog_r : Alog_f;
    const float* Dp   = dir ? D_r : D_f;
    float4 av = *(const float4*)(Alog + c * DS + q * 4);
    float a0 = -__expf(av.x), a1 = -__expf(av.y), a2 = -__expf(av.z), a3 = -__expf(av.w);
    float Dv = Dp[c];
    float h0 = 0.f, h1 = 0.f, h2 = 0.f, h3 = 0.f;
    size_t ob = (((size_t)dir * BB + b) * NCHUNK * DI + c) * DS + q * 4;
    for (int kk = 0; kk < k; kk++) {
        size_t o = ob + (size_t)kk * DI * DS;
        float4 P = *(const float4*)(g_P + o);
        float4 S = *(const float4*)(g_S + o);
        h0 = fmaf(P.x, h0, S.x);
        h1 = fmaf(P.y, h1, S.y);
        h2 = fmaf(P.z, h2, S.z);
        h3 = fmaf(P.w, h3, S.w);
    }
    size_t t0 = (size_t)(b * LL + k * CHL);
    const float* dlt = g_delta[dir] + t0 * DI + c;
    const float* uu  = g_uc[dir]    + t0 * DI + c;
    const float* xd  = g_xdbl[dir]  + t0 * XD;
    __half* yo       = g_y[dir]     + t0 * DI + c;
#pragma unroll 4
    for (int t = 0; t < CHL; t++) {
        float d  = dlt[(size_t)t * DI];
        float uv = uu[(size_t)t * DI];
        float4 Bq = *(const float4*)(xd + (size_t)t * XD + DTR + q * 4);
        float4 Cq = *(const float4*)(xd + (size_t)t * XD + DTR + DS + q * 4);
        float du = d * uv;
        float dA0 = __expf(d * a0), dA1 = __expf(d * a1);
        float dA2 = __expf(d * a2), dA3 = __expf(d * a3);
        h0 = fmaf(dA0, h0, du * Bq.x);
        h1 = fmaf(dA1, h1, du * Bq.y);
        h2 = fmaf(dA2, h2, du * Bq.z);
        h3 = fmaf(dA3, h3, du * Bq.w);
        float p = h0 * Cq.x;
        p = fmaf(h1, Cq.y, p);
        p = fmaf(h2, Cq.z, p);
        p = fmaf(h3, Cq.w, p);
        p += __shfl_xor_sync(0xffffffffu, p, 1);
        p += __shfl_xor_sync(0xffffffffu, p, 2);
        if (q == 0) yo[(size_t)t * DI] = __float2half_rn(fmaf(uv, Dv, p));
    }
}

// ================= combine + gate -> fp16 ==================================
__global__ void combine_kernel()
{
    int c = blockIdx.x * 256 + threadIdx.x;
    int l = blockIdx.y;
    int b = blockIdx.z;
    size_t idx = (size_t)(b * LL + l) * DI + c;
    float yf = __half2float(g_y[0][idx]);
    float yr = __half2float(g_y[1][(size_t)(b * LL + (LL - 1 - l)) * DI + c]);
    float z  = g_xz[(size_t)(b * LL + l) * (2 * DI) + DI + c];
    float sig = 1.f / (1.f + __expf(-z));
    g_ych[idx] = __float2half_rn((yf + yr) * (z * sig));
}

// ================= launch ==================================================
extern "C" void kernel_launch(void* const* d_in, const int* in_sizes, int n_in,
                              void* d_out, int out_size)
{
    const float* x      = (const float*)d_in[0];
    const float* in_w   = (const float*)d_in[1];
    const float* out_w  = (const float*)d_in[2];
    const float* cw_f   = (const float*)d_in[3];
    const float* cb_f   = (const float*)d_in[4];
    const float* xp_f   = (const float*)d_in[5];
    const float* dtw_f  = (const float*)d_in[6];
    const float* dtb_f  = (const float*)d_in[7];
    const float* Alog_f = (const float*)d_in[8];
    const float* D_f    = (const float*)d_in[9];
    const float* cw_r   = (const float*)d_in[10];
    const float* cb_r   = (const float*)d_in[11];
    const float* xp_r   = (const float*)d_in[12];
    const float* dtw_r  = (const float*)d_in[13];
    const float* dtb_r  = (const float*)d_in[14];
    const float* Alog_r = (const float*)d_in[15];
    const float* D_r    = (const float*)d_in[16];
    float* out = (float*)d_out;

    cudaFuncSetAttribute(gemm_f16, cudaFuncAttributeMaxDynamicSharedMemorySize, GEMM_SMEM);
    cudaFuncSetAttribute(dtproj_kernel, cudaFuncAttributeMaxDynamicSharedMemorySize, DT_SMEM);

    float *xz, *c2p, *xpart;
    __half *ah, *w1h, *w1l, *ych, *w2h, *w2l, *uh, *xpwh, *xpwl;
    cudaGetSymbolAddress((void**)&xz,    g_xz);
    cudaGetSymbolAddress((void**)&c2p,   g_c2p);
    cudaGetSymbolAddress((void**)&xpart, g_xpart);
    cudaGetSymbolAddress((void**)&ah,    g_ah);
    cudaGetSymbolAddress((void**)&w1h,   g_w1h);
    cudaGetSymbolAddress((void**)&w1l,   g_w1l);
    cudaGetSymbolAddress((void**)&ych,   g_ych);
    cudaGetSymbolAddress((void**)&w2h,   g_w2h);
    cudaGetSymbolAddress((void**)&w2l,   g_w2l);
    cudaGetSymbolAddress((void**)&uh,    g_uh);
    cudaGetSymbolAddress((void**)&xpwh,  g_xpwh);
    cudaGetSymbolAddress((void**)&xpwl,  g_xpwl);

    const size_t UD = (size_t)ROWS * DI;
    const size_t WD = (size_t)XPN * DI;
    const size_t PD = (size_t)KSPLIT * ROWS * XPN;

    // 1. convert all GEMM inputs (x single fp16; weights fp16 hi/lo)
    cvt_all<<<(N4_TOT + 255) / 256, 256>>>(x, in_w, out_w, xp_f, xp_r);
    // 2. xz = x @ in_w^T
    gemm_f16<<<dim3((2 * DI) / 64, ROWS / 128, 1), 256, GEMM_SMEM>>>(
        ah, w1h, w1l, xz, ROWS, 2 * DI, DM, DM, 1, 0, 0, 0);
    // 3. conv + silu
    conv_silu_kernel<<<dim3(DI / 128, LL / 4, BB * 2), 128>>>(cw_f, cb_f, cw_r, cb_r);
    // 4. x_proj: both dirs in one launch, then reduce
    gemm_f16<<<dim3(XPN / 64, ROWS / 128, 2 * KSPLIT), 256, GEMM_SMEM>>>(
        (const __half*)uh, (const __half*)xpwh, (const __half*)xpwl,
        xpart, ROWS, XPN, DI, DI / KSPLIT, KSPLIT, UD, WD, PD);
    xreduce<<<(2 * ROWS * XD + 255) / 256, 256>>>();
    // 5. dt projection + softplus
    dtproj_kernel<<<dim3(ROWS / 32, DI / 256, 2), 256, DT_SMEM>>>(dtw_f, dtb_f, dtw_r, dtb_r);
    // 6. chunked selective scan
    scan_pass1<<<dim3(DI / 32, BB * NCHUNK, 2), 128>>>(Alog_f, Alog_r);
    scan_pass2<<<dim3(DI / 32, BB * NCHUNK, 2), 128>>>(Alog_f, D_f, Alog_r, D_r);
    // 7. combine + gate -> fp16
    combine_kernel<<<dim3(DI / 256, LL, BB), 256>>>();
    // 8. out = ycomb @ out_w^T (split-K x3 + reduce)
    gemm_f16<<<dim3(DM / 64, ROWS / 128, G2SPLIT), 256, GEMM_SMEM>>>(
        ych, w2h, w2l, c2p, ROWS, DM, DI, DI / G2SPLIT, G2SPLIT, 0, 0, 0);
    reduce_g2<<<(ROWS * DM / 4 + 255) / 256, 256>>>(out);
}